// round 3
// baseline (speedup 1.0000x reference)
#include <cuda_runtime.h>
#include <math.h>

#define IMG 120
#define GT 1024
#define PP 1024
#define NB 8

// ---------------- scratch (device globals; no allocations allowed) ----------
__device__ __align__(16) float g_h1[NB * 8 * 57 * 57];   // conv1 pooled output
__device__ __align__(16) float g_h2[NB * 10 * 26 * 26];  // conv2 pooled (== flatten)
__device__ __align__(16) float g_fc1[NB * 32];           // relu(fc1)
__device__ __align__(16) float g_vals[NB * PP * 3];      // sampled values
__device__ int g_idx[PP];                                // px*GT + py per point

// ---------------- packed f32x2 helpers (sm_103a FFMA2) -----------------------
__device__ __forceinline__ unsigned long long pack2(float a, float b) {
    unsigned long long r;
    asm("mov.b64 %0, {%1,%2};" : "=l"(r) : "f"(a), "f"(b));
    return r;
}
__device__ __forceinline__ void ffma2(unsigned long long& d,
                                      unsigned long long a,
                                      unsigned long long b) {
    asm("fma.rn.f32x2 %0, %1, %2, %0;" : "+l"(d) : "l"(a), "l"(b));
}
__device__ __forceinline__ float2 unpack2(unsigned long long v) {
    float2 r;
    asm("mov.b64 {%0,%1}, %2;" : "=f"(r.x), "=f"(r.y) : "l"(v));
    return r;
}

// ---------------- fill chunk: each fill-thread writes 16 consecutive floats --
// aligned_x is constant per (n,c) plane except the 1024 scattered points
// (overwritten later by scatter). Constant = bilinear sample at image center
// (zero grid entry -> ix=iy=59.5 -> mean of the 4 center pixels).
// 65536 fill-threads per 1,048,576-float plane; 1,572,864 total.
__device__ __forceinline__ void do_fill(float* __restrict__ out96,
                                        const float* __restrict__ x,
                                        unsigned int ft) {
    int plane = (int)(ft >> 16);  // (ft*16)/1048576
    const float* xp = x + ((size_t)plane * IMG + 59) * IMG + 59;
    float v = 0.25f * (__ldg(xp) + __ldg(xp + 1) + __ldg(xp + IMG) +
                       __ldg(xp + IMG + 1));
    float4 vv = make_float4(v, v, v, v);
    float4* o = reinterpret_cast<float4*>(out96) + (size_t)ft * 4;
    __stcs(o + 0, vv);
    __stcs(o + 1, vv);
    __stcs(o + 2, vv);
    __stcs(o + 3, vv);
}

// fill distribution across the 4 main kernels (thread-id bases)
#define C1_BLOCKS 204            /* conv1 compute blocks (8*57*57 / 128) */
#define F1_BLOCKS 4352
#define F1_BASE 0u
#define C2_BLOCKS 169            /* conv2 compute blocks */
#define F2_BLOCKS 2816
#define F2_BASE 557056u
#define C3_BLOCKS 256            /* fc1 compute blocks */
#define F3_BLOCKS 2432
#define F3_BASE 917504u
#define C4_BLOCKS 1              /* headproj compute block */
#define F4_BLOCKS 336
#define F4_BASE 1228800u

// ---------------- conv1 + maxpool2 + relu + fill share -----------------------
// x: (8,3,120,120), w: (8,3,7,7). VALID conv -> (114,114), pool2 -> (57,57).
// One thread per pooled pixel; 8 oc x 4 quadrants as 16 packed f32x2 accums.
__global__ void __launch_bounds__(128) conv1_kernel(const float* __restrict__ x,
                                                    const float* __restrict__ w,
                                                    const float* __restrict__ b,
                                                    float* __restrict__ out96) {
    if (blockIdx.x >= C1_BLOCKS) {
        unsigned int ft = F1_BASE + (blockIdx.x - C1_BLOCKS) * 128u + threadIdx.x;
        do_fill(out96, x, ft);
        return;
    }
    __shared__ unsigned long long sw2[8 * 3 * 49];  // weight duplicated (w,w)
    __shared__ float sb[8];
    for (int i = threadIdx.x; i < 8 * 3 * 49; i += 128) {
        float wv = w[i];
        sw2[i] = pack2(wv, wv);
    }
    if (threadIdx.x < 8) sb[threadIdx.x] = b[threadIdx.x];
    __syncthreads();

    int tid = blockIdx.x * 128 + threadIdx.x;
    if (tid >= NB * 57 * 57) return;
    int n = tid / (57 * 57);
    int r = tid % (57 * 57);
    int oy = r / 57, ox = r % 57;

    unsigned long long accA[8], accB[8];  // A: (q0,q1) top row; B: (q2,q3)
#pragma unroll
    for (int oc = 0; oc < 8; oc++) { accA[oc] = 0ull; accB[oc] = 0ull; }

    const float* xb = x + (size_t)n * 3 * IMG * IMG + (2 * oy) * IMG + 2 * ox;
    for (int kc = 0; kc < 3; kc++) {
        const float* xc = xb + kc * IMG * IMG;
#pragma unroll
        for (int ky = 0; ky < 7; ky++) {
            const float* xr = xc + ky * IMG;
#pragma unroll
            for (int kx = 0; kx < 7; kx++) {
                unsigned long long xa = pack2(xr[kx], xr[kx + 1]);
                unsigned long long xbp = pack2(xr[kx + IMG], xr[kx + IMG + 1]);
#pragma unroll
                for (int oc = 0; oc < 8; oc++) {
                    unsigned long long wv = sw2[(oc * 3 + kc) * 49 + ky * 7 + kx];
                    ffma2(accA[oc], xa, wv);
                    ffma2(accB[oc], xbp, wv);
                }
            }
        }
    }
#pragma unroll
    for (int oc = 0; oc < 8; oc++) {
        float2 a = unpack2(accA[oc]);
        float2 c = unpack2(accB[oc]);
        float v = fmaxf(fmaxf(a.x, a.y), fmaxf(c.x, c.y)) + sb[oc];
        g_h1[((n * 8 + oc) * 57 + oy) * 57 + ox] = fmaxf(v, 0.f);
    }
}

// ---------------- conv2 + maxpool2 + relu (4-way kc-split) + fill share ------
// in: (8,8,57,57), w: (10,8,5,5). VALID -> (53,53), pool2 -> (26,26).
// 4 consecutive lanes per pooled pixel (2 input channels each); packed f32x2
// partials combined via shfl_xor.
__global__ void __launch_bounds__(128) conv2_kernel(const float* __restrict__ w,
                                                    const float* __restrict__ b,
                                                    const float* __restrict__ x,
                                                    float* __restrict__ out96) {
    if (blockIdx.x >= C2_BLOCKS) {
        unsigned int ft = F2_BASE + (blockIdx.x - C2_BLOCKS) * 128u + threadIdx.x;
        do_fill(out96, x, ft);
        return;
    }
    __shared__ unsigned long long sw2[10 * 8 * 25];
    __shared__ float sb[10];
    for (int i = threadIdx.x; i < 10 * 8 * 25; i += 128) {
        float wv = w[i];
        sw2[i] = pack2(wv, wv);
    }
    if (threadIdx.x < 10) sb[threadIdx.x] = b[threadIdx.x];
    __syncthreads();

    int t = blockIdx.x * 128 + threadIdx.x;  // 0 .. 21631
    int split = t & 3;                       // 2 kc per split
    int pix = t >> 2;                        // 0 .. 5407
    int n = pix / 676;
    int r = pix % 676;
    int oy = r / 26, ox = r % 26;

    unsigned long long accA[10], accB[10];
#pragma unroll
    for (int oc = 0; oc < 10; oc++) { accA[oc] = 0ull; accB[oc] = 0ull; }

    const float* xb = g_h1 + (size_t)n * 8 * 57 * 57 + (2 * oy) * 57 + 2 * ox;
#pragma unroll
    for (int kk = 0; kk < 2; kk++) {
        int kc = split * 2 + kk;
        const float* xc = xb + kc * 57 * 57;
#pragma unroll
        for (int ky = 0; ky < 5; ky++) {
            const float* xr = xc + ky * 57;
#pragma unroll
            for (int kx = 0; kx < 5; kx++) {
                unsigned long long xa = pack2(xr[kx], xr[kx + 1]);
                unsigned long long xbp = pack2(xr[kx + 57], xr[kx + 58]);
#pragma unroll
                for (int oc = 0; oc < 10; oc++) {
                    unsigned long long wv = sw2[(oc * 8 + kc) * 25 + ky * 5 + kx];
                    ffma2(accA[oc], xa, wv);
                    ffma2(accB[oc], xbp, wv);
                }
            }
        }
    }

    // combine 4 kc-splits via butterfly shuffles (per 32-bit half)
#pragma unroll
    for (int oc = 0; oc < 10; oc++) {
        float2 a = unpack2(accA[oc]);
        float2 c = unpack2(accB[oc]);
        float q0 = a.x, q1 = a.y, q2 = c.x, q3 = c.y;
        q0 += __shfl_xor_sync(0xffffffffu, q0, 1);
        q1 += __shfl_xor_sync(0xffffffffu, q1, 1);
        q2 += __shfl_xor_sync(0xffffffffu, q2, 1);
        q3 += __shfl_xor_sync(0xffffffffu, q3, 1);
        q0 += __shfl_xor_sync(0xffffffffu, q0, 2);
        q1 += __shfl_xor_sync(0xffffffffu, q1, 2);
        q2 += __shfl_xor_sync(0xffffffffu, q2, 2);
        q3 += __shfl_xor_sync(0xffffffffu, q3, 2);
        if (split == 0) {
            float v = fmaxf(fmaxf(q0, q1), fmaxf(q2, q3)) + sb[oc];
            // layout: n*6760 + oc*676 + oy*26 + ox (matches jnp reshape)
            g_h2[((n * 10 + oc) * 26 + oy) * 26 + ox] = fmaxf(v, 0.f);
        }
    }
}

// ---------------- FC1 + relu + fill share ------------------------------------
// one block per (n, j) output; float4 strided dot + warp/smem reduction.
__global__ void __launch_bounds__(128) fc1_kernel(const float* __restrict__ w,
                                                  const float* __restrict__ b,
                                                  const float* __restrict__ x,
                                                  float* __restrict__ out96) {
    if (blockIdx.x >= C3_BLOCKS) {
        unsigned int ft = F3_BASE + (blockIdx.x - C3_BLOCKS) * 128u + threadIdx.x;
        do_fill(out96, x, ft);
        return;
    }
    int n = blockIdx.x >> 5;
    int j = blockIdx.x & 31;
    const float4* wr = reinterpret_cast<const float4*>(w + (size_t)j * 6760);
    const float4* hr = reinterpret_cast<const float4*>(g_h2 + (size_t)n * 6760);
    float s = 0.f;
    for (int i = threadIdx.x; i < 1690; i += 128) {  // 6760/4
        float4 a = wr[i], c = hr[i];
        s = fmaf(a.x, c.x, s);
        s = fmaf(a.y, c.y, s);
        s = fmaf(a.z, c.z, s);
        s = fmaf(a.w, c.w, s);
    }
#pragma unroll
    for (int off = 16; off > 0; off >>= 1)
        s += __shfl_xor_sync(0xffffffffu, s, off);
    __shared__ float red[4];
    if ((threadIdx.x & 31) == 0) red[threadIdx.x >> 5] = s;
    __syncthreads();
    if (threadIdx.x == 0)
        g_fc1[n * 32 + j] =
            fmaxf(red[0] + red[1] + red[2] + red[3] + b[j], 0.f);
}

// ---------------- FC2 + Rodrigues + T_theta + proj + idx + fill share --------
// block 0 (1024 threads) does the whole head; remaining blocks fill.
__global__ void __launch_bounds__(1024) headproj_kernel(
    const float* __restrict__ w2, const float* __restrict__ b2,
    const float* __restrict__ x, const float* __restrict__ uv,
    const float* __restrict__ xyz, float* __restrict__ out) {
    float* out96 = out + 96;
    if (blockIdx.x >= C4_BLOCKS) {
        unsigned int ft =
            F4_BASE + (blockIdx.x - C4_BLOCKS) * 1024u + threadIdx.x;
        do_fill(out96, x, ft);
        return;
    }
    __shared__ float sfc1[256];   // g_fc1 staged
    __shared__ float sw2[224];    // w_fc2 (7x32)
    __shared__ float sth[56];     // theta
    __shared__ float sT[96];      // T_theta
    int t = threadIdx.x;
    if (t < 256) sfc1[t] = g_fc1[t];
    if (t >= 256 && t < 480) sw2[t - 256] = w2[t - 256];
    __syncthreads();

    if (t < 56) {
        int n = t / 7, i = t % 7;
        float s = b2[i];
#pragma unroll
        for (int j = 0; j < 32; j++)
            s = fmaf(sfc1[n * 32 + j], sw2[i * 32 + j], s);
        sth[t] = s;
    }
    __syncthreads();
    if (t < 8) {
        const float* th = &sth[t * 7];
        float sc = fabsf(th[0]);
        float vx = th[1], vy = th[2], vz = th[3];
        float ang = sqrtf(vx * vx + vy * vy + vz * vz + 1e-8f);
        float kx = vx / ang, ky = vy / ang, kz = vz / ang;
        float sn = sinf(ang);
        float cc = 1.f - cosf(ang);
        float R[3][3];
        R[0][0] = 1.f - cc * (ky * ky + kz * kz);
        R[0][1] = sn * (-kz) + cc * (kx * ky);
        R[0][2] = sn * (ky) + cc * (kx * kz);
        R[1][0] = sn * (kz) + cc * (kx * ky);
        R[1][1] = 1.f - cc * (kx * kx + kz * kz);
        R[1][2] = sn * (-kx) + cc * (ky * kz);
        R[2][0] = sn * (-ky) + cc * (kx * kz);
        R[2][1] = sn * (kx) + cc * (ky * kz);
        R[2][2] = 1.f - cc * (kx * kx + ky * ky);
#pragma unroll
        for (int i = 0; i < 3; i++) {
#pragma unroll
            for (int j = 0; j < 3; j++) {
                float v = R[i][j] * sc;
                sT[t * 12 + i * 4 + j] = v;
                out[t * 12 + i * 4 + j] = v;
            }
            float v3 = th[4 + i];
            sT[t * 12 + i * 4 + 3] = v3;
            out[t * 12 + i * 4 + 3] = v3;
        }
    }
    __syncthreads();

    // thread t handles point p = t for all 8 batches
    {
        int p = t;
        float X = xyz[p * 3], Y = xyz[p * 3 + 1], Z = xyz[p * 3 + 2];
        int px = (int)floorf(uv[p * 2] * (float)GT);
        int py = (int)floorf(uv[p * 2 + 1] * (float)GT);
        g_idx[p] = px * GT + py;
#pragma unroll
        for (int n = 0; n < NB; n++) {
            const float* T = &sT[n * 12];
            float p0 = T[0] * X + T[1] * Y + T[2] * Z + T[3];
            float p1 = T[4] * X + T[5] * Y + T[6] * Z + T[7];
            float xs = p0 / (float)IMG * 2.0f - 1.0f;
            float ys = -(p1 / (float)IMG * 2.0f - 1.0f);
            float ix = ((xs + 1.0f) * (float)IMG - 1.0f) * 0.5f;
            float iy = ((ys + 1.0f) * (float)IMG - 1.0f) * 0.5f;
            float ix0 = floorf(ix), iy0 = floorf(iy);
            float fx = ix - ix0, fy = iy - iy0;
            float v0 = 0.f, v1 = 0.f, v2 = 0.f;
            const float* xb = x + (size_t)n * 3 * IMG * IMG;
#define CORNER(IYF, IXF, WT)                                          \
    {                                                                 \
        float wv = (WT);                                              \
        float iyf = (IYF), ixf = (IXF);                               \
        if (ixf >= 0.f && ixf < (float)IMG && iyf >= 0.f &&           \
            iyf < (float)IMG) {                                       \
            int ii = (int)ixf, jj = (int)iyf;                         \
            const float* pc = xb + jj * IMG + ii;                     \
            v0 = fmaf(pc[0], wv, v0);                                 \
            v1 = fmaf(pc[IMG * IMG], wv, v1);                         \
            v2 = fmaf(pc[2 * IMG * IMG], wv, v2);                     \
        }                                                             \
    }
            CORNER(iy0, ix0, (1.f - fy) * (1.f - fx));
            CORNER(iy0, ix0 + 1.f, (1.f - fy) * fx);
            CORNER(iy0 + 1.f, ix0, fy * (1.f - fx));
            CORNER(iy0 + 1.f, ix0 + 1.f, fy * fx);
#undef CORNER
            g_vals[(n * PP + p) * 3 + 0] = v0;
            g_vals[(n * PP + p) * 3 + 1] = v1;
            g_vals[(n * PP + p) * 3 + 2] = v2;
        }
    }
}

// ---------------- scatter of sampled values (after all fill shares) ----------
__global__ void scatter_kernel(float* __restrict__ out96) {
    int t = blockIdx.x * blockDim.x + threadIdx.x;
    if (t >= NB * PP * 3) return;
    int c = t % 3;
    int p = (t / 3) % PP;
    int n = t / (3 * PP);
    out96[(size_t)(n * 3 + c) * (GT * GT) + g_idx[p]] =
        g_vals[(n * PP + p) * 3 + c];
}

// ---------------- launch -----------------------------------------------------
extern "C" void kernel_launch(void* const* d_in, const int* in_sizes, int n_in,
                              void* d_out, int out_size) {
    const float* x   = (const float*)d_in[0];
    const float* uv  = (const float*)d_in[1];
    const float* xyz = (const float*)d_in[2];
    const float* w1  = (const float*)d_in[3];
    const float* b1  = (const float*)d_in[4];
    const float* w2  = (const float*)d_in[5];
    const float* b2  = (const float*)d_in[6];
    const float* wf1 = (const float*)d_in[7];
    const float* bf1 = (const float*)d_in[8];
    const float* wf2 = (const float*)d_in[9];
    const float* bf2 = (const float*)d_in[10];
    float* out = (float*)d_out;

    conv1_kernel<<<C1_BLOCKS + F1_BLOCKS, 128>>>(x, w1, b1, out + 96);
    conv2_kernel<<<C2_BLOCKS + F2_BLOCKS, 128>>>(w2, b2, x, out + 96);
    fc1_kernel<<<C3_BLOCKS + F3_BLOCKS, 128>>>(wf1, bf1, x, out + 96);
    headproj_kernel<<<C4_BLOCKS + F4_BLOCKS, 1024>>>(wf2, bf2, x, uv, xyz, out);
    scatter_kernel<<<(NB * PP * 3 + 255) / 256, 256>>>(out + 96);
}

// round 6
// speedup vs baseline: 1.3346x; 1.3346x over previous
#include <cuda_runtime.h>
#include <math.h>

#define IMG 120
#define GT 1024
#define PP 1024
#define NB 8

// ---------------- scratch (device globals; no allocations allowed) ----------
__device__ __align__(16) float g_h1[NB * 8 * 57 * 57];   // conv1 pooled output
__device__ __align__(16) float g_h2[NB * 10 * 26 * 26];  // conv2 pooled (== flatten)
__device__ __align__(16) float g_fc1[NB * 32];           // relu(fc1)
__device__ __align__(16) float g_T[NB * 12];             // T_theta

// ---------------- packed f32x2 helpers (sm_103a FFMA2) -----------------------
__device__ __forceinline__ unsigned long long pack2(float a, float b) {
    unsigned long long r;
    asm("mov.b64 %0, {%1,%2};" : "=l"(r) : "f"(a), "f"(b));
    return r;
}
__device__ __forceinline__ void ffma2(unsigned long long& d,
                                      unsigned long long a,
                                      unsigned long long b) {
    asm("fma.rn.f32x2 %0, %1, %2, %0;" : "+l"(d) : "l"(a), "l"(b));
}
__device__ __forceinline__ float2 unpack2(unsigned long long v) {
    float2 r;
    asm("mov.b64 {%0,%1}, %2;" : "=f"(r.x), "=f"(r.y) : "l"(v));
    return r;
}

// ---------------- fill: one 128-thread block covers 8 KB, COALESCED ----------
// aligned_x is constant per (n,c) plane except the 1024 scattered points,
// which are written by the FINAL proj launch (strictly after all fill blocks
// — fusing fill into the proj launch raced and corrupted the scatter).
// Constant = bilinear sample at image center (zero grid -> ix=iy=59.5 ->
// mean of the 4 center pixels).
// Fill-block b covers float4 [b*512, (b+1)*512); plane = b>>9 (512 blocks per
// 262144-f4 plane). Each store: 32 lanes write 32 consecutive float4 = 512B =
// 4 full 128B lines -> fully coalesced.
__device__ __forceinline__ void do_fill(float* __restrict__ out96,
                                        const float* __restrict__ x,
                                        unsigned int b) {
    int plane = (int)(b >> 9);
    const float* xp = x + ((size_t)plane * IMG + 59) * IMG + 59;
    float v = 0.25f * (__ldg(xp) + __ldg(xp + 1) + __ldg(xp + IMG) +
                       __ldg(xp + IMG + 1));
    float4 vv = make_float4(v, v, v, v);
    int w = threadIdx.x >> 5, l = threadIdx.x & 31;
    float4* o = reinterpret_cast<float4*>(out96) + (size_t)b * 512 + w * 128 + l;
#pragma unroll
    for (int j = 0; j < 4; j++) __stcs(o + j * 32, vv);
}

// fill distribution across kernels 1-4 ONLY (proj must see completed fill)
#define C1_BLOCKS 204            /* conv1 compute blocks (ceil(8*57*57/128)) */
#define F1_COUNT 5504
#define F1_BASE 0u
#define C2_BLOCKS 169            /* conv2 compute blocks */
#define F2_COUNT 3232
#define F2_BASE 5504u
#define C3_BLOCKS 256            /* fc1 compute blocks */
#define F3_COUNT 2592
#define F3_BASE 8736u
#define C4_BLOCKS 1              /* head compute block */
#define F4_COUNT 960
#define F4_BASE 11328u
/* 5504+3232+2592+960 = 12288 blocks * 8KB = 100.66MB  ✓ */
#define C5_BLOCKS 64             /* proj compute blocks (8192/128), no fill */

// ---------------- conv1 + maxpool2 + relu + fill share -----------------------
// x: (8,3,120,120), w: (8,3,7,7). VALID conv -> (114,114), pool2 -> (57,57).
// One thread per pooled pixel; 8 oc x 4 quadrants as 16 packed f32x2 accums.
__global__ void __launch_bounds__(128) conv1_kernel(const float* __restrict__ x,
                                                    const float* __restrict__ w,
                                                    const float* __restrict__ b,
                                                    float* __restrict__ out96) {
    if (blockIdx.x >= C1_BLOCKS) {
        do_fill(out96, x, F1_BASE + (blockIdx.x - C1_BLOCKS));
        return;
    }
    __shared__ unsigned long long sw2[8 * 3 * 49];  // weight duplicated (w,w)
    __shared__ float sb[8];
    for (int i = threadIdx.x; i < 8 * 3 * 49; i += 128) {
        float wv = w[i];
        sw2[i] = pack2(wv, wv);
    }
    if (threadIdx.x < 8) sb[threadIdx.x] = b[threadIdx.x];
    __syncthreads();

    int tid = blockIdx.x * 128 + threadIdx.x;
    if (tid >= NB * 57 * 57) return;
    int n = tid / (57 * 57);
    int r = tid % (57 * 57);
    int oy = r / 57, ox = r % 57;

    unsigned long long accA[8], accB[8];  // A: (q0,q1) top row; B: (q2,q3)
#pragma unroll
    for (int oc = 0; oc < 8; oc++) { accA[oc] = 0ull; accB[oc] = 0ull; }

    const float* xb = x + (size_t)n * 3 * IMG * IMG + (2 * oy) * IMG + 2 * ox;
    for (int kc = 0; kc < 3; kc++) {
        const float* xc = xb + kc * IMG * IMG;
#pragma unroll
        for (int ky = 0; ky < 7; ky++) {
            const float* xr = xc + ky * IMG;
#pragma unroll
            for (int kx = 0; kx < 7; kx++) {
                unsigned long long xa = pack2(xr[kx], xr[kx + 1]);
                unsigned long long xbp = pack2(xr[kx + IMG], xr[kx + IMG + 1]);
#pragma unroll
                for (int oc = 0; oc < 8; oc++) {
                    unsigned long long wv = sw2[(oc * 3 + kc) * 49 + ky * 7 + kx];
                    ffma2(accA[oc], xa, wv);
                    ffma2(accB[oc], xbp, wv);
                }
            }
        }
    }
#pragma unroll
    for (int oc = 0; oc < 8; oc++) {
        float2 a = unpack2(accA[oc]);
        float2 c = unpack2(accB[oc]);
        float v = fmaxf(fmaxf(a.x, a.y), fmaxf(c.x, c.y)) + sb[oc];
        g_h1[((n * 8 + oc) * 57 + oy) * 57 + ox] = fmaxf(v, 0.f);
    }
}

// ---------------- conv2 + maxpool2 + relu (4-way kc-split) + fill share ------
// in: (8,8,57,57), w: (10,8,5,5). VALID -> (53,53), pool2 -> (26,26).
// 4 consecutive lanes per pooled pixel (2 input channels each); packed f32x2
// partials combined via shfl_xor.
__global__ void __launch_bounds__(128) conv2_kernel(const float* __restrict__ w,
                                                    const float* __restrict__ b,
                                                    const float* __restrict__ x,
                                                    float* __restrict__ out96) {
    if (blockIdx.x >= C2_BLOCKS) {
        do_fill(out96, x, F2_BASE + (blockIdx.x - C2_BLOCKS));
        return;
    }
    __shared__ unsigned long long sw2[10 * 8 * 25];
    __shared__ float sb[10];
    for (int i = threadIdx.x; i < 10 * 8 * 25; i += 128) {
        float wv = w[i];
        sw2[i] = pack2(wv, wv);
    }
    if (threadIdx.x < 10) sb[threadIdx.x] = b[threadIdx.x];
    __syncthreads();

    int t = blockIdx.x * 128 + threadIdx.x;  // 0 .. 21631
    int split = t & 3;                       // 2 kc per split
    int pix = t >> 2;                        // 0 .. 5407
    int n = pix / 676;
    int r = pix % 676;
    int oy = r / 26, ox = r % 26;

    unsigned long long accA[10], accB[10];
#pragma unroll
    for (int oc = 0; oc < 10; oc++) { accA[oc] = 0ull; accB[oc] = 0ull; }

    const float* xb = g_h1 + (size_t)n * 8 * 57 * 57 + (2 * oy) * 57 + 2 * ox;
#pragma unroll
    for (int kk = 0; kk < 2; kk++) {
        int kc = split * 2 + kk;
        const float* xc = xb + kc * 57 * 57;
#pragma unroll
        for (int ky = 0; ky < 5; ky++) {
            const float* xr = xc + ky * 57;
#pragma unroll
            for (int kx = 0; kx < 5; kx++) {
                unsigned long long xa = pack2(xr[kx], xr[kx + 1]);
                unsigned long long xbp = pack2(xr[kx + 57], xr[kx + 58]);
#pragma unroll
                for (int oc = 0; oc < 10; oc++) {
                    unsigned long long wv = sw2[(oc * 8 + kc) * 25 + ky * 5 + kx];
                    ffma2(accA[oc], xa, wv);
                    ffma2(accB[oc], xbp, wv);
                }
            }
        }
    }

    // combine 4 kc-splits via butterfly shuffles (per 32-bit half)
#pragma unroll
    for (int oc = 0; oc < 10; oc++) {
        float2 a = unpack2(accA[oc]);
        float2 c = unpack2(accB[oc]);
        float q0 = a.x, q1 = a.y, q2 = c.x, q3 = c.y;
        q0 += __shfl_xor_sync(0xffffffffu, q0, 1);
        q1 += __shfl_xor_sync(0xffffffffu, q1, 1);
        q2 += __shfl_xor_sync(0xffffffffu, q2, 1);
        q3 += __shfl_xor_sync(0xffffffffu, q3, 1);
        q0 += __shfl_xor_sync(0xffffffffu, q0, 2);
        q1 += __shfl_xor_sync(0xffffffffu, q1, 2);
        q2 += __shfl_xor_sync(0xffffffffu, q2, 2);
        q3 += __shfl_xor_sync(0xffffffffu, q3, 2);
        if (split == 0) {
            float v = fmaxf(fmaxf(q0, q1), fmaxf(q2, q3)) + sb[oc];
            // layout: n*6760 + oc*676 + oy*26 + ox (matches jnp reshape)
            g_h2[((n * 10 + oc) * 26 + oy) * 26 + ox] = fmaxf(v, 0.f);
        }
    }
}

// ---------------- FC1 + relu + fill share ------------------------------------
// one block per (n, j) output; float4 strided dot + warp/smem reduction.
__global__ void __launch_bounds__(128) fc1_kernel(const float* __restrict__ w,
                                                  const float* __restrict__ b,
                                                  const float* __restrict__ x,
                                                  float* __restrict__ out96) {
    if (blockIdx.x >= C3_BLOCKS) {
        do_fill(out96, x, F3_BASE + (blockIdx.x - C3_BLOCKS));
        return;
    }
    int n = blockIdx.x >> 5;
    int j = blockIdx.x & 31;
    const float4* wr = reinterpret_cast<const float4*>(w + (size_t)j * 6760);
    const float4* hr = reinterpret_cast<const float4*>(g_h2 + (size_t)n * 6760);
    float s = 0.f;
    for (int i = threadIdx.x; i < 1690; i += 128) {  // 6760/4
        float4 a = wr[i], c = hr[i];
        s = fmaf(a.x, c.x, s);
        s = fmaf(a.y, c.y, s);
        s = fmaf(a.z, c.z, s);
        s = fmaf(a.w, c.w, s);
    }
#pragma unroll
    for (int off = 16; off > 0; off >>= 1)
        s += __shfl_xor_sync(0xffffffffu, s, off);
    __shared__ float red[4];
    if ((threadIdx.x & 31) == 0) red[threadIdx.x >> 5] = s;
    __syncthreads();
    if (threadIdx.x == 0)
        g_fc1[n * 32 + j] =
            fmaxf(red[0] + red[1] + red[2] + red[3] + b[j], 0.f);
}

// ---------------- FC2 + Rodrigues + T_theta + fill share ---------------------
// block 0 (128 threads) computes theta/T; remaining blocks fill.
__global__ void __launch_bounds__(128) head_kernel(const float* __restrict__ w2,
                                                   const float* __restrict__ b2,
                                                   const float* __restrict__ x,
                                                   float* __restrict__ out) {
    if (blockIdx.x >= C4_BLOCKS) {
        do_fill(out + 96, x, F4_BASE + (blockIdx.x - C4_BLOCKS));
        return;
    }
    __shared__ float sfc1[256];  // g_fc1 staged (coalesced load, then smem)
    __shared__ float sw2[224];   // w_fc2 (7x32)
    __shared__ float sth[56];    // theta
    int t = threadIdx.x;
    sfc1[t] = g_fc1[t];
    sfc1[t + 128] = g_fc1[t + 128];
    if (t < 112) {
        sw2[t] = w2[t];
        sw2[t + 112] = w2[t + 112];
    }
    __syncthreads();

    if (t < 56) {
        int n = t / 7, i = t % 7;
        float s = b2[i];
#pragma unroll
        for (int j = 0; j < 32; j++)
            s = fmaf(sfc1[n * 32 + j], sw2[i * 32 + j], s);
        sth[t] = s;
    }
    __syncthreads();
    if (t < 8) {
        const float* th = &sth[t * 7];
        float sc = fabsf(th[0]);
        float vx = th[1], vy = th[2], vz = th[3];
        float ang = sqrtf(vx * vx + vy * vy + vz * vz + 1e-8f);
        float kx = vx / ang, ky = vy / ang, kz = vz / ang;
        float sn = sinf(ang);
        float cc = 1.f - cosf(ang);
        float R[3][3];
        R[0][0] = 1.f - cc * (ky * ky + kz * kz);
        R[0][1] = sn * (-kz) + cc * (kx * ky);
        R[0][2] = sn * (ky) + cc * (kx * kz);
        R[1][0] = sn * (kz) + cc * (kx * ky);
        R[1][1] = 1.f - cc * (kx * kx + kz * kz);
        R[1][2] = sn * (-kx) + cc * (ky * kz);
        R[2][0] = sn * (-ky) + cc * (kx * kz);
        R[2][1] = sn * (kx) + cc * (ky * kz);
        R[2][2] = 1.f - cc * (kx * kx + ky * ky);
#pragma unroll
        for (int i = 0; i < 3; i++) {
#pragma unroll
            for (int j = 0; j < 3; j++) {
                float v = R[i][j] * sc;
                g_T[t * 12 + i * 4 + j] = v;
                out[t * 12 + i * 4 + j] = v;
            }
            float v3 = th[4 + i];
            g_T[t * 12 + i * 4 + 3] = v3;
            out[t * 12 + i * 4 + 3] = v3;
        }
    }
}

// ---------------- projection + bilinear sample + DIRECT scatter --------------
// Pure compute launch (runs after ALL fill blocks have completed in prior
// launches): each thread (n,p) writes its 3 sampled channel values into out.
__global__ void __launch_bounds__(128) proj_kernel(const float* __restrict__ x,
                                                   const float* __restrict__ uv,
                                                   const float* __restrict__ xyz,
                                                   float* __restrict__ out96) {
    int t = blockIdx.x * 128 + threadIdx.x;  // 0 .. 8191
    int n = t >> 10, p = t & 1023;
    const float* T = g_T + n * 12;
    float X = xyz[p * 3], Y = xyz[p * 3 + 1], Z = xyz[p * 3 + 2];
    float p0 = T[0] * X + T[1] * Y + T[2] * Z + T[3];
    float p1 = T[4] * X + T[5] * Y + T[6] * Z + T[7];
    float xs = p0 / (float)IMG * 2.0f - 1.0f;
    float ys = -(p1 / (float)IMG * 2.0f - 1.0f);
    float ix = ((xs + 1.0f) * (float)IMG - 1.0f) * 0.5f;
    float iy = ((ys + 1.0f) * (float)IMG - 1.0f) * 0.5f;
    float ix0 = floorf(ix), iy0 = floorf(iy);
    float fx = ix - ix0, fy = iy - iy0;
    float v0 = 0.f, v1 = 0.f, v2 = 0.f;
    const float* xb = x + (size_t)n * 3 * IMG * IMG;

#define CORNER(IYF, IXF, WT)                                              \
    {                                                                     \
        float wv = (WT);                                                  \
        float iyf = (IYF), ixf = (IXF);                                   \
        if (ixf >= 0.f && ixf < (float)IMG && iyf >= 0.f &&               \
            iyf < (float)IMG) {                                           \
            int ii = (int)ixf, jj = (int)iyf;                             \
            const float* pc = xb + jj * IMG + ii;                         \
            v0 = fmaf(pc[0], wv, v0);                                     \
            v1 = fmaf(pc[IMG * IMG], wv, v1);                             \
            v2 = fmaf(pc[2 * IMG * IMG], wv, v2);                         \
        }                                                                 \
    }
    CORNER(iy0, ix0, (1.f - fy) * (1.f - fx));
    CORNER(iy0, ix0 + 1.f, (1.f - fy) * fx);
    CORNER(iy0 + 1.f, ix0, fy * (1.f - fx));
    CORNER(iy0 + 1.f, ix0 + 1.f, fy * fx);
#undef CORNER

    int px = (int)floorf(uv[p * 2] * (float)GT);
    int py = (int)floorf(uv[p * 2 + 1] * (float)GT);
    size_t idx = (size_t)px * GT + py;
    float* ob = out96 + (size_t)n * 3 * GT * GT + idx;
    ob[0] = v0;
    ob[GT * GT] = v1;
    ob[2 * GT * GT] = v2;
}

// ---------------- launch -----------------------------------------------------
extern "C" void kernel_launch(void* const* d_in, const int* in_sizes, int n_in,
                              void* d_out, int out_size) {
    const float* x   = (const float*)d_in[0];
    const float* uv  = (const float*)d_in[1];
    const float* xyz = (const float*)d_in[2];
    const float* w1  = (const float*)d_in[3];
    const float* b1  = (const float*)d_in[4];
    const float* w2  = (const float*)d_in[5];
    const float* b2  = (const float*)d_in[6];
    const float* wf1 = (const float*)d_in[7];
    const float* bf1 = (const float*)d_in[8];
    const float* wf2 = (const float*)d_in[9];
    const float* bf2 = (const float*)d_in[10];
    float* out = (float*)d_out;

    conv1_kernel<<<C1_BLOCKS + F1_COUNT, 128>>>(x, w1, b1, out + 96);
    conv2_kernel<<<C2_BLOCKS + F2_COUNT, 128>>>(w2, b2, x, out + 96);
    fc1_kernel<<<C3_BLOCKS + F3_COUNT, 128>>>(wf1, bf1, x, out + 96);
    head_kernel<<<C4_BLOCKS + F4_COUNT, 128>>>(wf2, bf2, x, out);
    proj_kernel<<<C5_BLOCKS, 128>>>(x, uv, xyz, out + 96);
}